// round 17
// baseline (speedup 1.0000x reference)
#include <cuda_runtime.h>
#include <cuda_bf16.h>
#include <cstdint>

// ---------------------------------------------------------------------------
// RNN_MultiRegional_SAC — persistent bf16 mma.sync, warp-specialized pipeline,
// PARALLEL per-lane staging (8 concurrent flag polls / copies per ring).
// h = relu(0.9 h + 0.1 (h @ W^T + drive)), 512 steps, B=32, 3H=3072.
// 80 blocks, ONE per SM, W resident in smem (128KB). 576 threads:
//   warps 0..15 compute (grpA = K-half 0 + epilogue, grpB = K-half 1),
//   warp 16 stages ring A (lanes 0..7 = tile residues), warp 17 ring B.
// Per-tile mbarriers (8 full + 8 empty per ring), each advancing ONE phase
// per step: consumer full-wait parity t&1; staging lane i waits
// empty[(i+4)&7] parity (t+1)&1 (i<4) or empty[i-4] parity t&1 (i>=4).
// Flags: per-(t,tile), 24 distinct addrs; publish via red.release (no fence).
// fp32 master h in registers; rnn stores deferred one step; depth-4 g_hb ring.
// Output (float32): [mean 32*512][std 32*512][hn_last 32*3072][rnn 32*512*3072]
// ---------------------------------------------------------------------------

#define Hh   1024
#define H3   3072
#define Bz   32
#define Tz   512
#define NEXC 717
#define HH   (Hh*Hh)
#define NBLK 80
#define NTHR 576

#define OFF_HA  131072u              // ring A: 4 x 8KB
#define OFF_HB  163840u              // ring B: 4 x 8KB
#define OFF_CB  196608u              // combine: 2 x 4KB (parity)
#define SMEM_BYTES 204800

// Packed, per-block-contiguous, pre-swizzled W: [bid 80][kt 16][4096 bf16] = 10.5MB
__device__ __align__(256) __nv_bfloat16 g_Wp[80u * 16u * 4096u];
// bf16 operand h, tiled+swizzled, DEPTH-4 ring: 24 tiles of 4096; tile tk holds
// k in [tk*128,(tk+1)*128): elem off = b*128 + ((((k>>3)&15)^(b&7))<<3) + (k&7)
__device__ __align__(256) __nv_bfloat16 g_hb[4][24 * 4096];
__device__ int g_tflag[Tz * 24];    // per-(step,tile) producer arrivals

// ---------------- helpers ----------------
__device__ __forceinline__ unsigned smem_u32(const void* p) {
    return (unsigned)__cvta_generic_to_shared(p);
}
__device__ __forceinline__ void bulk_cp(unsigned dstS, const void* srcG, unsigned bytes, unsigned mbarS) {
    asm volatile("cp.async.bulk.shared::cta.global.mbarrier::complete_tx::bytes [%0], [%1], %2, [%3];"
                 :: "r"(dstS), "l"(srcG), "r"(bytes), "r"(mbarS) : "memory");
}
__device__ __forceinline__ void mbar_init(unsigned mbarS, unsigned cnt) {
    asm volatile("mbarrier.init.shared.b64 [%0], %1;" :: "r"(mbarS), "r"(cnt) : "memory");
}
__device__ __forceinline__ void mbar_expect(unsigned mbarS, unsigned bytes) {
    asm volatile("mbarrier.arrive.expect_tx.shared.b64 _, [%0], %1;" :: "r"(mbarS), "r"(bytes) : "memory");
}
__device__ __forceinline__ void mbar_arrive(unsigned mbarS) {
    asm volatile("mbarrier.arrive.shared.b64 _, [%0];" :: "r"(mbarS) : "memory");
}
__device__ __forceinline__ void mbar_wait(unsigned mbarS, unsigned parity) {
    asm volatile(
        "{\n\t.reg .pred P;\n"
        "W_%=:\n\t"
        "mbarrier.try_wait.parity.acquire.cta.shared::cta.b64 P, [%0], %1, 0x989680;\n\t"
        "@P bra D_%=;\n\t"
        "bra W_%=;\n"
        "D_%=:\n\t}"
        :: "r"(mbarS), "r"(parity) : "memory");
}
__device__ __forceinline__ void poll_flag(const int* p, int expect) {
    int v;
    do {
        asm volatile("ld.acquire.gpu.global.b32 %0, [%1];" : "=r"(v) : "l"(p));
    } while (v < expect);
}
__device__ __forceinline__ void flag_release_add(int* p) {
    asm volatile("red.release.gpu.global.add.s32 [%0], %1;" :: "l"(p), "r"(1) : "memory");
}
__device__ __forceinline__ int texpect(int tile) {
    return (tile < 8) ? 4 : ((tile < 16) ? 2 : 4);
}
__device__ __forceinline__ float hclip(float x) {
    return fminf(fmaxf(x, 1e-10f), 1.0f);
}
#define BARS(id, cnt) asm volatile("bar.sync " #id ", " #cnt ";" ::: "memory")

// ---------------- prep: pack W into per-block swizzled tiles + zero flags ------
__global__ void prep_pack(const float* __restrict__ w_str2thal,
                          const float* __restrict__ w_m12m1,
                          const float* __restrict__ w_m12str,
                          const float* __restrict__ w_thal2m1,
                          const float* __restrict__ fixedw) {
    int e = blockIdx.x * blockDim.x + threadIdx.x;
    if (e >= 80 * 16 * 4096) return;
    if (e < Tz * 24) g_tflag[e] = 0;

    int bid = e >> 16;              // /65536
    int rem = e & 65535;
    int kt  = rem >> 12;            // 0..15
    int wi  = rem & 4095;
    int row = wi >> 7;              // n-row within 32-row W tile
    int chunk = ((wi >> 3) & 15) ^ (row & 7);
    int kl  = (chunk << 3) | (wi & 7);
    int k   = ((kt & 7) << 7) + kl; // k within 1024-col W block

    float val;
    if (bid < 32) {                 // str: kt<8 -> W00, kt>=8 -> W02
        int n = bid * 32 + row;
        int src = n * Hh + k;
        if (kt < 8) val = -fixedw[src];
        else { float v = hclip(w_m12str[src]); val = (k < NEXC) ? v : 0.0f; }
    } else if (bid < 64) {          // m1: kt<8 -> W21, kt>=8 -> W22
        int n = (bid - 32) * 32 + row;
        int src = n * Hh + k;
        if (kt < 8) val = hclip(w_thal2m1[src]);
        else { float v = hclip(w_m12m1[src]); val = (k < NEXC) ? v : -v; }
    } else {                        // thal: 64n strip; kt<8 rows 0..31, kt>=8 rows 32..63
        int n = (bid - 64) * 64 + ((kt >> 3) << 5) + row;
        int src = n * Hh + k;
        float v = hclip(w_str2thal[src]);
        val = (k < (Hh / 2)) ? v : -v;
    }
    g_Wp[e] = __float2bfloat16(val);
}

// ---------------- init: hn ([b][n]) -> tiled bf16 operand (ring slot 0) --------
__global__ void init_kernel(const float* __restrict__ hn) {
    int idx = blockIdx.x * blockDim.x + threadIdx.x;
    if (idx >= Bz * H3) return;
    int b = idx / H3, n = idx - b * H3;
    int off = (n >> 7) * 4096 + b * 128 + ((((n >> 3) & 15) ^ (b & 7)) << 3) + (n & 7);
    g_hb[0][off] = __float2bfloat16(hn[idx]);
}

// ---------------- persistent tensor-core kernel ----------------------------------
// mbar layout: [0..7] fullA, [8..15] emptyA, [16..23] fullB, [24..31] emptyB, [32] W
__global__ void __launch_bounds__(NTHR, 1) rnn_persist(const float* __restrict__ inp,
                                                       const float* __restrict__ iw,
                                                       const float* __restrict__ hn0,
                                                       float* __restrict__ rnn) {
    extern __shared__ __align__(256) unsigned char smem[];
    __shared__ __align__(8) unsigned long long mbar[33];

    const int tx   = threadIdx.x;
    const int bid  = blockIdx.x;
    const int wid  = tx >> 5;
    const int lane = tx & 31;
    const bool thal = (bid >= 64);

    // ---- block decode ----
    int n0, htA, htB, myTile;
    if (bid < 32)      { n0 = bid * 32;              htA = 0;  htB = 16; myTile = bid >> 2; }
    else if (bid < 64) { n0 = 2048 + (bid - 32)*32;  htA = 8;  htB = 16; myTile = 16 + ((bid - 32) >> 2); }
    else               { n0 = 1024 + (bid - 64)*64;  htA = 0;  htB = 0;  myTile = 8 + ((bid - 64) >> 1); }

    const unsigned sBase = smem_u32(smem);
    const unsigned mBase = smem_u32(mbar);

    // ---- one-time prologue: barriers ----
    if (tx == 0) {
        const unsigned eCntA = thal ? 16u : 8u;
#pragma unroll
        for (int i = 0; i < 8; i++) {
            mbar_init(mBase + i * 8, 1);              // fullA[i]
            mbar_init(mBase + (8 + i) * 8, eCntA);    // emptyA[i]
            mbar_init(mBase + (16 + i) * 8, 1);       // fullB[i]
            mbar_init(mBase + (24 + i) * 8, 8);       // emptyB[i]
        }
        mbar_init(mBase + 32 * 8, 1);                 // W
    }
    __syncthreads();   // all 576 threads (before any branch)

    // =================== staging warps (parallel lanes) ===================
    if (wid >= 16) {
        const bool isB = (wid == 17);
        if (lane < 8 && !(isB && thal)) {
            const int ht    = isB ? htB : htA;
            const int mb    = isB ? 16 : 0;           // full base; empty = mb+8
            const unsigned ring = sBase + (isB ? OFF_HB : OFF_HA);
            const int i     = lane;                    // tile residue 0..7
            const int tile  = ht + i;
            const int slot  = i & 3;
            const int ewait = (i < 4) ? (i + 4) : (i - 4);
            const int texp  = texpect(tile);
#pragma unroll 1
            for (int t = 0; t < Tz; t++) {
                if (t > 0) poll_flag(&g_tflag[(t - 1) * 24 + tile], texp);
                unsigned epar = (i < 4) ? (unsigned)((t + 1) & 1) : (unsigned)(t & 1);
                mbar_wait(mBase + (mb + 8 + ewait) * 8, epar);
                mbar_expect(mBase + (mb + i) * 8, 8192);
                bulk_cp(ring + slot * 8192, g_hb[t & 3] + tile * 4096, 8192,
                        mBase + (mb + i) * 8);
            }
        }
        return;
    }

    // =================== compute warps ===================
    // ---- resident W load (128KB) ----
    if (tx == 0) {
        mbar_expect(mBase + 32 * 8, 131072);
        bulk_cp(sBase,         g_Wp + (size_t)bid * 65536,         65536, mBase + 32 * 8);
        bulk_cp(sBase + 65536, g_Wp + (size_t)bid * 65536 + 32768, 65536, mBase + 32 * 8);
    }
    mbar_wait(mBase + 32 * 8, 0);

    // ---- warp roles ----
    const int bt = wid & 1;
    int nh, ks, wtb;
    if (!thal) { ks = wid >> 3; nh = (wid >> 1) & 3; wtb = ks * 8; }
    else       { ks = 0;        nh = wid >> 1;       wtb = (nh >> 2) * 8; }
    const int brow = (thal ? (nh & 3) : nh) * 8 + (lane & 7);
    const bool grpB = (!thal && ks == 1);
    const unsigned ringOff = grpB ? OFF_HB : OFF_HA;
    const int mbRing = grpB ? 16 : 0;                 // full base; empty = +8

    // ---- ldmatrix lane addressing ----
    const int am = lane >> 3;
    const int arow = bt * 16 + (am & 1) * 8 + (lane & 7);   // A row (batch)
    const int qa   = am >> 1;
    const int sa   = arow & 7;
    const int grp  = lane >> 3;
    const int sb   = brow & 7;
    const unsigned habase = sBase + ringOff + arow * 256;
    const unsigned wbbase = sBase + brow * 256;

    // ---- epilogue constants ----
    const int g  = lane >> 2, tg = lane & 3;
    const int pn = nh * 8 + 2 * tg;
    const int pb = bt * 16 + g;
    const int ncol = n0 + pn;
    const bool owner = thal || (ks == 0);
    float iwv[2][4];
#pragma unroll
    for (int j = 0; j < 2; j++)
#pragma unroll
        for (int i = 0; i < 4; i++) iwv[j][i] = iw[i * H3 + ncol + j];

    // ---- fp32 master h in registers (owner threads only) ----
    float hm[4];
#pragma unroll
    for (int half = 0; half < 2; half++)
#pragma unroll
        for (int j = 0; j < 2; j++)
            hm[half * 2 + j] = owner ? hn0[(pb + half * 8) * H3 + ncol + j] : 0.0f;

    // =================== time loop ===================
#pragma unroll 1
    for (int t = 0; t < Tz; t++) {
        const unsigned par = (unsigned)(t & 1);
        __nv_bfloat16* hbn = g_hb[(t + 1) & 3];

        // ---- deferred rnn stores for step t-1 (off critical path) ----
        if (owner && t > 0) {
#pragma unroll
            for (int half = 0; half < 2; half++) {
                int b = pb + half * 8;
                *(float2*)&rnn[((size_t)(b * Tz + (t - 1))) * H3 + ncol] =
                    make_float2(hm[half * 2], hm[half * 2 + 1]);
            }
        }

        // hoist drive loads (independent of h)
        float4 iva = make_float4(0.f, 0.f, 0.f, 0.f), ivb = iva;
        if (owner) {
            iva = ((const float4*)inp)[pb * Tz + t];
            ivb = ((const float4*)inp)[(pb + 8) * Tz + t];
        }

        float d[2][4];
#pragma unroll
        for (int e = 0; e < 2; e++)
#pragma unroll
            for (int j = 0; j < 4; j++) d[e][j] = 0.f;

#pragma unroll 1
        for (int kt = 0; kt < 8; kt++) {
            const int slot = kt & 3;
            mbar_wait(mBase + (mbRing + kt) * 8, par);

            const unsigned ha = habase + slot * 8192;
            const unsigned wa = wbbase + (wtb + kt) * 8192;
#pragma unroll
            for (int kp = 0; kp < 4; kp++) {
                unsigned b0, b1, b2, b3;
                asm volatile("ldmatrix.sync.aligned.m8n8.x4.shared.b16 {%0,%1,%2,%3}, [%4];"
                             : "=r"(b0), "=r"(b1), "=r"(b2), "=r"(b3)
                             : "r"(wa + (((4 * kp + grp) ^ sb) << 4)));
                unsigned a0, a1, a2, a3;
                asm volatile("ldmatrix.sync.aligned.m8n8.x4.shared.b16 {%0,%1,%2,%3}, [%4];"
                             : "=r"(a0), "=r"(a1), "=r"(a2), "=r"(a3)
                             : "r"(ha + (((4 * kp + qa) ^ sa) << 4)));
                asm volatile("mma.sync.aligned.m16n8k16.row.col.f32.bf16.bf16.f32 "
                             "{%0,%1,%2,%3}, {%4,%5,%6,%7}, {%8,%9}, {%0,%1,%2,%3};"
                             : "+f"(d[0][0]), "+f"(d[0][1]), "+f"(d[0][2]), "+f"(d[0][3])
                             : "r"(a0), "r"(a1), "r"(a2), "r"(a3), "r"(b0), "r"(b1));
                unsigned c0, c1, c2, c3;
                asm volatile("ldmatrix.sync.aligned.m8n8.x4.shared.b16 {%0,%1,%2,%3}, [%4];"
                             : "=r"(c0), "=r"(c1), "=r"(c2), "=r"(c3)
                             : "r"(ha + (((4 * kp + 2 + qa) ^ sa) << 4)));
                asm volatile("mma.sync.aligned.m16n8k16.row.col.f32.bf16.bf16.f32 "
                             "{%0,%1,%2,%3}, {%4,%5,%6,%7}, {%8,%9}, {%0,%1,%2,%3};"
                             : "+f"(d[1][0]), "+f"(d[1][1]), "+f"(d[1][2]), "+f"(d[1][3])
                             : "r"(c0), "r"(c1), "r"(c2), "r"(c3), "r"(b2), "r"(b3));
            }

            if (lane == 0) mbar_arrive(mBase + (mbRing + 8 + kt) * 8);
        }

        float ds[4];
#pragma unroll
        for (int j = 0; j < 4; j++) ds[j] = d[0][j] + d[1][j];

        // ---- cross-group combine (non-thal): B writes, parity barrier, A reads ----
        if (!thal) {
            float* scb = (float*)(smem + OFF_CB) + (int)par * 1024;
            if (grpB) {
                *(float4*)&scb[(tx - 256) * 4] = make_float4(ds[0], ds[1], ds[2], ds[3]);
                if (par == 0) BARS(3, 512); else BARS(4, 512);
                // group B done: loops to t+1 immediately
            } else {
                if (par == 0) BARS(3, 512); else BARS(4, 512);
                const float4 p = *(const float4*)&scb[tx * 4];
                ds[0] += p.x; ds[1] += p.y; ds[2] += p.z; ds[3] += p.w;
            }
        }

        // ---- epilogue (owners): relu update in registers; write bf16 operand ----
        if (owner) {
#pragma unroll
            for (int half = 0; half < 2; half++) {
                float4 iv = half ? ivb : iva;
                float v2[2];
#pragma unroll
                for (int j = 0; j < 2; j++) {
                    float drv = iv.x * iwv[j][0] + iv.y * iwv[j][1]
                              + iv.z * iwv[j][2] + iv.w * iwv[j][3];
                    float v = fmaxf(0.9f * hm[half * 2 + j] + 0.1f * (ds[half * 2 + j] + drv), 0.0f);
                    hm[half * 2 + j] = v;
                    v2[j] = v;
                }
                int b = pb + half * 8;
                int n = ncol;
                int off = (n >> 7) * 4096 + b * 128 + ((((n >> 3) & 15) ^ (b & 7)) << 3) + (n & 7);
                __nv_bfloat162 pk;
                pk.x = __float2bfloat16(v2[0]);
                pk.y = __float2bfloat16(v2[1]);
                *(__nv_bfloat162*)&hbn[off] = pk;
            }
        }

        // ---- flag publish: owner-group barrier + release-red (no MEMBAR) ----
        if (thal) {
            BARS(5, 512);
            if (tx == 0) flag_release_add(&g_tflag[t * 24 + myTile]);
        } else if (!grpB) {
            BARS(1, 256);
            if (tx == 0) flag_release_add(&g_tflag[t * 24 + myTile]);
        }
    }

    // ---- drain: rnn stores for final step ----
    if (owner) {
#pragma unroll
        for (int half = 0; half < 2; half++) {
            int b = pb + half * 8;
            *(float2*)&rnn[((size_t)(b * Tz + (Tz - 1))) * H3 + ncol] =
                make_float2(hm[half * 2], hm[half * 2 + 1]);
        }
    }
}

// ---------------- heads: mean/std over masked (m1) region ----------------------
__global__ void head_kernel(const float* __restrict__ rnn,
                            const float* __restrict__ mean_w, const float* __restrict__ mean_b,
                            const float* __restrict__ std_w,  const float* __restrict__ std_b,
                            float* __restrict__ mean_out, float* __restrict__ std_out) {
    int warp = blockIdx.x * 8 + (threadIdx.x >> 5);   // = b*512 + t
    int lane = threadIdx.x & 31;
    const float* row = rnn + (size_t)warp * H3 + 2048;
    float sm = 0.0f, ss = 0.0f;
#pragma unroll 8
    for (int i = lane; i < Hh; i += 32) {
        float v = row[i];
        sm += v * mean_w[2048 + i];
        ss += v * std_w[2048 + i];
    }
#pragma unroll
    for (int off = 16; off; off >>= 1) {
        sm += __shfl_down_sync(0xFFFFFFFFu, sm, off);
        ss += __shfl_down_sync(0xFFFFFFFFu, ss, off);
    }
    if (lane == 0) {
        mean_out[warp] = sm + mean_b[0];
        float s = ss + std_b[0];
        std_out[warp] = fminf(fmaxf(s, -5.0f), 10.0f);
    }
}

// ---------------- hn_last copy --------------------------------------------------
__global__ void hn_kernel(const float* __restrict__ rnn, float* __restrict__ hn_out) {
    int idx = blockIdx.x * blockDim.x + threadIdx.x;
    if (idx >= Bz * H3) return;
    int b = idx / H3, n = idx - b * H3;
    hn_out[idx] = rnn[((size_t)(b * Tz + (Tz - 1))) * H3 + n];
}

// ---------------- launch ---------------------------------------------------------
extern "C" void kernel_launch(void* const* d_in, const int* in_sizes, int n_in,
                              void* d_out, int out_size) {
    const float* inp        = (const float*)d_in[0];   // [32,512,4]
    const float* hn         = (const float*)d_in[1];   // [1,32,3072]
    // d_in[2] = w_str2str (unused: its mask is all-zeros in the reference)
    const float* w_str2thal = (const float*)d_in[3];
    const float* w_m12m1    = (const float*)d_in[4];
    const float* w_m12str   = (const float*)d_in[5];
    const float* w_thal2m1  = (const float*)d_in[6];
    const float* fixedw     = (const float*)d_in[7];
    const float* inp_weight = (const float*)d_in[8];   // [4,3072]
    const float* mean_w     = (const float*)d_in[9];   // [1,3072]
    const float* mean_b     = (const float*)d_in[10];  // [1]
    const float* std_w      = (const float*)d_in[11];
    const float* std_b      = (const float*)d_in[12];
    // d_in[13] = sampling flag

    float* out      = (float*)d_out;
    float* mean_out = out;                         // 32*512
    float* std_out  = out + 16384;                 // 32*512
    float* hn_out   = out + 32768;                 // 32*3072
    float* rnn      = out + 131072;                // 32*512*3072

    cudaFuncSetAttribute(rnn_persist, cudaFuncAttributeMaxDynamicSharedMemorySize, SMEM_BYTES);

    prep_pack<<<(80 * 16 * 4096 + 255) / 256, 256>>>(w_str2thal, w_m12m1, w_m12str, w_thal2m1, fixedw);
    init_kernel<<<(Bz * H3 + 255) / 256, 256>>>(hn);

    rnn_persist<<<NBLK, NTHR, SMEM_BYTES>>>(inp, inp_weight, hn, rnn);

    head_kernel<<<2048, 256>>>(rnn, mean_w, mean_b, std_w, std_b, mean_out, std_out);
    hn_kernel<<<(Bz * H3 + 255) / 256, 256>>>(rnn, hn_out);
}